// round 7
// baseline (speedup 1.0000x reference)
#include <cuda_runtime.h>
#include <cstdint>

// Packed fp32x2 add (sm_100a): one SASS instruction for 2 fp32 adds.
#define ADD_F32X2(out, a, b) \
    asm("add.rn.f32x2 %0, %1, %2;" : "=l"(out) : "l"(a), "l"(b))

constexpr int S = 512, H = 8, D = 64;
constexpr int TI = 64;    // i-tile (output columns)
constexpr int TJ = 128;   // j-tile (output rows)
constexpr int STR = 68;   // floats; 272B rows: 16B aligned (LDS.128 legal), bank start
                          // 4*tx mod 32 -> 8-lane phases cover all 32 banks, conflict-free.
constexpr int SMEM_BYTES = (TI + TJ) * STR * 4;   // 52224 B -> dynamic smem (opt-in)

__global__ __launch_bounds__(256, 2)
void l1attn_kernel(const float* __restrict__ q, const float* __restrict__ k,
                   float* __restrict__ out) {
    extern __shared__ __align__(16) float smem[];
    float* qs = smem;             // TI * STR
    float* ks = smem + TI * STR;  // TJ * STR

    const int bh = blockIdx.z;          // b*H + h
    const int b  = bh >> 3;
    const int h  = bh & 7;
    const int i0 = blockIdx.x * TI;
    const int j0 = blockIdx.y * TJ;
    const int tid = threadIdx.x;

    // ---- Fill smem: q tile (64 rows) and NEGATED k tile (128 rows) ----
    #pragma unroll
    for (int idx = tid; idx < TI * (D / 2); idx += 256) {
        const int r  = idx >> 5;
        const int dv = idx & 31;
        const float2 qv = *reinterpret_cast<const float2*>(
            q + (((b * S + i0 + r) * H + h) * D) + 2 * dv);
        *reinterpret_cast<float2*>(qs + r * STR + 2 * dv) = qv;
    }
    #pragma unroll
    for (int idx = tid; idx < TJ * (D / 2); idx += 256) {
        const int r  = idx >> 5;
        const int dv = idx & 31;
        float2 kv = *reinterpret_cast<const float2*>(
            k + (((b * S + j0 + r) * H + h) * D) + 2 * dv);
        kv.x = -kv.x; kv.y = -kv.y;     // pre-negate: packed ADD acts as SUB
        *reinterpret_cast<float2*>(ks + r * STR + 2 * dv) = kv;
    }
    __syncthreads();

    const int tx = tid & 15;            // i direction: i = tx + 16*c, c<4
    const int ty = tid >> 4;            // j direction: j = ty + 16*e, e<8

    const float* qbase = qs + tx * STR;
    const float* kbase = ks + ty * STR;

    unsigned long long acc[4][8];
    #pragma unroll
    for (int c = 0; c < 4; ++c)
        #pragma unroll
        for (int e = 0; e < 8; ++e) acc[c][e] = 0ull;

    // Math over one k-register set (4 e-values starting at EB).
    #define MATH4(K4, EB)                                                   \
        _Pragma("unroll")                                                   \
        for (int c = 0; c < 4; ++c)                                         \
            _Pragma("unroll")                                               \
            for (int ee = 0; ee < 4; ++ee) {                                \
                unsigned long long d0, d1, s, t;                            \
                ADD_F32X2(d0, q4[c].x, K4[ee].x);                           \
                d0 &= 0x7FFFFFFF7FFFFFFFull;                                \
                ADD_F32X2(d1, q4[c].y, K4[ee].y);                           \
                d1 &= 0x7FFFFFFF7FFFFFFFull;                                \
                ADD_F32X2(s, d0, d1);                                       \
                ADD_F32X2(t, acc[c][(EB) + ee], s);                         \
                acc[c][(EB) + ee] = t;                                      \
            }

    #pragma unroll 4
    for (int d4 = 0; d4 < D / 4; ++d4) {
        ulonglong2 q4[4], k4[4];
        #pragma unroll
        for (int c = 0; c < 4; ++c)
            q4[c] = *reinterpret_cast<const ulonglong2*>(
                qbase + 16 * c * STR + 4 * d4);
        // First 4 j-rows: ty + 16*{0..3}
        #pragma unroll
        for (int ee = 0; ee < 4; ++ee)
            k4[ee] = *reinterpret_cast<const ulonglong2*>(
                kbase + 16 * ee * STR + 4 * d4);
        MATH4(k4, 0)
        // Next 4 j-rows: ty + 16*{4..7} (reuse registers -> lower liveness)
        #pragma unroll
        for (int ee = 0; ee < 4; ++ee)
            k4[ee] = *reinterpret_cast<const ulonglong2*>(
                kbase + 16 * (ee + 4) * STR + 4 * d4);
        MATH4(k4, 4)
    }
    #undef MATH4

    // ---- Writeback: out[bh][j][i] = -0.125 * (lo + hi) ----
    #pragma unroll
    for (int e = 0; e < 8; ++e) {
        const int j = j0 + ty + 16 * e;
        float* orow = out + ((size_t)bh * S + j) * S + i0;
        #pragma unroll
        for (int c = 0; c < 4; ++c) {
            const unsigned long long a = acc[c][e];
            const float lo = __uint_as_float((unsigned)(a & 0xFFFFFFFFu));
            const float hi = __uint_as_float((unsigned)(a >> 32));
            orow[tx + 16 * c] = -0.125f * (lo + hi);
        }
    }
}

extern "C" void kernel_launch(void* const* d_in, const int* in_sizes, int n_in,
                              void* d_out, int out_size) {
    const float* q = (const float*)d_in[0];
    const float* k = (const float*)d_in[1];
    float* out     = (float*)d_out;
    // Opt in to >48KB dynamic smem (not a stream op; graph-capture safe).
    cudaFuncSetAttribute(l1attn_kernel,
                         cudaFuncAttributeMaxDynamicSharedMemorySize, SMEM_BYTES);
    dim3 grid(S / TI, S / TJ, 2 * H);   // (8, 4, 16) = 512 CTAs
    l1attn_kernel<<<grid, 256, SMEM_BYTES>>>(q, k, out);
}

// round 8
// speedup vs baseline: 1.0584x; 1.0584x over previous
#include <cuda_runtime.h>
#include <cstdint>

// Packed fp32x2 add (sm_100a): one SASS instruction for 2 fp32 adds.
#define ADD_F32X2(out, a, b) \
    asm("add.rn.f32x2 %0, %1, %2;" : "=l"(out) : "l"(a), "l"(b))

constexpr int S = 512, H = 8, D = 64;
constexpr int TI = 32;    // i-tile (output columns)
constexpr int TJ = 64;    // j-tile (output rows)
constexpr int STR = 68;   // floats; 272B rows: 16B aligned (LDS.128 legal), conflict-free.
constexpr int SMEM_FLOATS = (TI + TJ) * STR;   // 26112 B — fits static 48KB limit

__global__ __launch_bounds__(256, 5)
void l1attn_kernel(const float* __restrict__ q, const float* __restrict__ k,
                   float* __restrict__ out) {
    __shared__ __align__(16) float smem[SMEM_FLOATS];
    float* qs = smem;             // TI rows
    float* ks = smem + TI * STR;  // TJ rows

    const int bh = blockIdx.z;          // b*H + h
    const int b  = bh >> 3;
    const int h  = bh & 7;
    const int i0 = blockIdx.x * TI;
    const int j0 = blockIdx.y * TJ;
    const int tid = threadIdx.x;

    // ---- Fill smem: q tile (32 rows) and NEGATED k tile (64 rows) ----
    #pragma unroll
    for (int idx = tid; idx < TI * (D / 2); idx += 256) {
        const int r  = idx >> 5;
        const int dv = idx & 31;
        const float2 qv = *reinterpret_cast<const float2*>(
            q + (((b * S + i0 + r) * H + h) * D) + 2 * dv);
        *reinterpret_cast<float2*>(qs + r * STR + 2 * dv) = qv;
    }
    #pragma unroll
    for (int idx = tid; idx < TJ * (D / 2); idx += 256) {
        const int r  = idx >> 5;
        const int dv = idx & 31;
        float2 kv = *reinterpret_cast<const float2*>(
            k + (((b * S + j0 + r) * H + h) * D) + 2 * dv);
        kv.x = -kv.x; kv.y = -kv.y;     // pre-negate: packed ADD acts as SUB
        *reinterpret_cast<float2*>(ks + r * STR + 2 * dv) = kv;
    }
    __syncthreads();

    const int tx = tid & 15;            // i direction: i = tx + 16*c, c<2
    const int ty = tid >> 4;            // j direction: j = ty + 16*e, e<4

    const float* qbase = qs + tx * STR;
    const float* kbase = ks + ty * STR;

    unsigned long long acc[2][4];
    #pragma unroll
    for (int c = 0; c < 2; ++c)
        #pragma unroll
        for (int e = 0; e < 4; ++e) acc[c][e] = 0ull;

    // One k-register pair (2 e-values starting at EB) against both q rows.
    #define MATH2(EB)                                                       \
        _Pragma("unroll")                                                   \
        for (int c = 0; c < 2; ++c)                                         \
            _Pragma("unroll")                                               \
            for (int ee = 0; ee < 2; ++ee) {                                \
                unsigned long long d0, d1, s, t;                            \
                ADD_F32X2(d0, q4[c].x, k4[ee].x);                           \
                d0 &= 0x7FFFFFFF7FFFFFFFull;                                \
                ADD_F32X2(d1, q4[c].y, k4[ee].y);                           \
                d1 &= 0x7FFFFFFF7FFFFFFFull;                                \
                ADD_F32X2(s, d0, d1);                                       \
                ADD_F32X2(t, acc[c][(EB) + ee], s);                         \
                acc[c][(EB) + ee] = t;                                      \
            }

    #pragma unroll 4
    for (int d4 = 0; d4 < D / 4; ++d4) {
        ulonglong2 q4[2], k4[2];
        #pragma unroll
        for (int c = 0; c < 2; ++c)
            q4[c] = *reinterpret_cast<const ulonglong2*>(
                qbase + 16 * c * STR + 4 * d4);
        // k rows in 2-row halves to keep register liveness low.
        #pragma unroll
        for (int ee = 0; ee < 2; ++ee)
            k4[ee] = *reinterpret_cast<const ulonglong2*>(
                kbase + 16 * ee * STR + 4 * d4);
        MATH2(0)
        #pragma unroll
        for (int ee = 0; ee < 2; ++ee)
            k4[ee] = *reinterpret_cast<const ulonglong2*>(
                kbase + 16 * (ee + 2) * STR + 4 * d4);
        MATH2(2)
    }
    #undef MATH2

    // ---- Writeback: out[bh][j][i] = -0.125 * (lo + hi) ----
    #pragma unroll
    for (int e = 0; e < 4; ++e) {
        const int j = j0 + ty + 16 * e;
        float* orow = out + ((size_t)bh * S + j) * S + i0;
        #pragma unroll
        for (int c = 0; c < 2; ++c) {
            const unsigned long long a = acc[c][e];
            const float lo = __uint_as_float((unsigned)(a & 0xFFFFFFFFu));
            const float hi = __uint_as_float((unsigned)(a >> 32));
            orow[tx + 16 * c] = -0.125f * (lo + hi);
        }
    }
}

extern "C" void kernel_launch(void* const* d_in, const int* in_sizes, int n_in,
                              void* d_out, int out_size) {
    const float* q = (const float*)d_in[0];
    const float* k = (const float*)d_in[1];
    float* out     = (float*)d_out;
    dim3 grid(S / TI, S / TJ, 2 * H);   // (16, 8, 16) = 2048 CTAs
    l1attn_kernel<<<grid, 256>>>(q, k, out);
}

// round 9
// speedup vs baseline: 1.3900x; 1.3133x over previous
#include <cuda_runtime.h>
#include <cuda_fp16.h>
#include <cstdint>

// Packed fp32x2 add (sm_100a).
#define ADD_F32X2(out, a, b) \
    asm("add.rn.f32x2 %0, %1, %2;" : "=l"(out) : "l"(a), "l"(b))

constexpr int S = 512, H = 8, D = 64;
constexpr int TI = 32;     // i-tile (output columns)
constexpr int TJ = 64;     // j-tile (output rows)
constexpr int HSTR = 72;   // halves per smem row = 144B: 16B-aligned (LDS.128 legal),
                           // bank phase 4*tx mod 32 -> conflict-free 8-lane phases.

__global__ __launch_bounds__(256, 3)
void l1attn_kernel(const float* __restrict__ q, const float* __restrict__ k,
                   float* __restrict__ out) {
    __shared__ __align__(16) __half qs[TI * HSTR];
    __shared__ __align__(16) __half ks[TJ * HSTR];

    const int bh = blockIdx.z;          // b*H + h
    const int b  = bh >> 3;
    const int h  = bh & 7;
    const int i0 = blockIdx.x * TI;
    const int j0 = blockIdx.y * TJ;
    const int tid = threadIdx.x;

    // ---- Fill smem (fp32 -> fp16): q tile, NEGATED k tile ----
    #pragma unroll
    for (int idx = tid; idx < TI * (D / 2); idx += 256) {
        const int r  = idx >> 5;
        const int dv = idx & 31;
        const float2 qv = *reinterpret_cast<const float2*>(
            q + (((b * S + i0 + r) * H + h) * D) + 2 * dv);
        *reinterpret_cast<__half2*>(qs + r * HSTR + 2 * dv) = __float22half2_rn(qv);
    }
    #pragma unroll
    for (int idx = tid; idx < TJ * (D / 2); idx += 256) {
        const int r  = idx >> 5;
        const int dv = idx & 31;
        float2 kv = *reinterpret_cast<const float2*>(
            k + (((b * S + j0 + r) * H + h) * D) + 2 * dv);
        kv.x = -kv.x; kv.y = -kv.y;     // pre-negate: HADD2 acts as SUB
        *reinterpret_cast<__half2*>(ks + r * HSTR + 2 * dv) = __float22half2_rn(kv);
    }
    __syncthreads();

    const int tx = tid & 15;            // i: i = tx + 16*c, c<2
    const int ty = tid >> 4;            // j: j = ty + 16*e, e<4

    const __half* qbase = qs + tx * HSTR;
    const __half* kbase = ks + ty * HSTR;

    float2 acc[2][4];
    #pragma unroll
    for (int c = 0; c < 2; ++c)
        #pragma unroll
        for (int e = 0; e < 4; ++e) acc[c][e] = make_float2(0.f, 0.f);

    union U { uint4 u4; __half2 h2[4]; };

    // Per (c,e) pair for one 16-term group (8 half2 steps), then flush to fp32.
    #define PAIR16(C, EE, EB)                                                     \
        {                                                                         \
            __half2 a = __habs2(__hadd2(qv[C][0].h2[0], kv[EE][0].h2[0]));        \
            _Pragma("unroll")                                                     \
            for (int s = 1; s < 4; ++s)                                           \
                a = __hadd2(a, __habs2(__hadd2(qv[C][0].h2[s], kv[EE][0].h2[s])));\
            _Pragma("unroll")                                                     \
            for (int s = 0; s < 4; ++s)                                           \
                a = __hadd2(a, __habs2(__hadd2(qv[C][1].h2[s], kv[EE][1].h2[s])));\
            const float2 f = __half22float2(a);                                   \
            acc[C][(EB) + (EE)].x += f.x;                                         \
            acc[C][(EB) + (EE)].y += f.y;                                         \
        }

    // 4 groups of 16 halves (32B) cover D=64.
    #pragma unroll
    for (int g = 0; g < 4; ++g) {
        U qv[2][2], kv[2][2];
        #pragma unroll
        for (int c = 0; c < 2; ++c)
            #pragma unroll
            for (int j = 0; j < 2; ++j)
                qv[c][j].u4 = *reinterpret_cast<const uint4*>(
                    qbase + 16 * c * HSTR + g * 16 + 8 * j);
        // k rows e=0,1
        #pragma unroll
        for (int ee = 0; ee < 2; ++ee)
            #pragma unroll
            for (int j = 0; j < 2; ++j)
                kv[ee][j].u4 = *reinterpret_cast<const uint4*>(
                    kbase + 16 * ee * HSTR + g * 16 + 8 * j);
        #pragma unroll
        for (int c = 0; c < 2; ++c) { PAIR16(c, 0, 0) PAIR16(c, 1, 0) }
        // k rows e=2,3 (reuse registers)
        #pragma unroll
        for (int ee = 0; ee < 2; ++ee)
            #pragma unroll
            for (int j = 0; j < 2; ++j)
                kv[ee][j].u4 = *reinterpret_cast<const uint4*>(
                    kbase + 16 * (ee + 2) * HSTR + g * 16 + 8 * j);
        #pragma unroll
        for (int c = 0; c < 2; ++c) { PAIR16(c, 0, 2) PAIR16(c, 1, 2) }
    }
    #undef PAIR16

    // ---- Writeback: out[bh][j][i] = -0.125 * (x + y) ----
    #pragma unroll
    for (int e = 0; e < 4; ++e) {
        const int j = j0 + ty + 16 * e;
        float* orow = out + ((size_t)bh * S + j) * S + i0;
        #pragma unroll
        for (int c = 0; c < 2; ++c)
            orow[tx + 16 * c] = -0.125f * (acc[c][e].x + acc[c][e].y);
    }
}

extern "C" void kernel_launch(void* const* d_in, const int* in_sizes, int n_in,
                              void* d_out, int out_size) {
    const float* q = (const float*)d_in[0];
    const float* k = (const float*)d_in[1];
    float* out     = (float*)d_out;
    dim3 grid(S / TI, S / TJ, 2 * H);   // (16, 8, 16) = 2048 CTAs
    l1attn_kernel<<<grid, 256>>>(q, k, out);
}

// round 10
// speedup vs baseline: 1.4008x; 1.0077x over previous
#include <cuda_runtime.h>
#include <cuda_fp16.h>
#include <cstdint>

constexpr int S = 512, H = 8, D = 64;
constexpr int TI = 32;     // i-tile (output columns)
constexpr int TJ = 128;    // j-tile (output rows)
constexpr int HSTR = 72;   // halves per smem row = 144B: 16B-aligned (LDS.128 legal),
                           // conflict-free phases for tx-strided rows.

__global__ __launch_bounds__(256, 3)
void l1attn_kernel(const float* __restrict__ q, const float* __restrict__ k,
                   float* __restrict__ out) {
    __shared__ __align__(16) __half qs[TI * HSTR];
    __shared__ __align__(16) __half ks[TJ * HSTR];

    const int bh = blockIdx.z;          // b*H + h
    const int b  = bh >> 3;
    const int h  = bh & 7;
    const int i0 = blockIdx.x * TI;
    const int j0 = blockIdx.y * TJ;
    const int tid = threadIdx.x;

    union HU { __half2 h; unsigned u; };

    // ---- Fill smem (float4 LDG.128 -> packed 8B STS): q tile, NEGATED k tile ----
    #pragma unroll
    for (int idx = tid; idx < TI * (D / 4); idx += 256) {
        const int r  = idx >> 4;
        const int dv = idx & 15;
        const float4 v = *reinterpret_cast<const float4*>(
            q + (((b * S + i0 + r) * H + h) * D) + 4 * dv);
        HU h0, h1;
        h0.h = __floats2half2_rn(v.x, v.y);
        h1.h = __floats2half2_rn(v.z, v.w);
        *reinterpret_cast<uint2*>(qs + r * HSTR + 4 * dv) = make_uint2(h0.u, h1.u);
    }
    #pragma unroll
    for (int idx = tid; idx < TJ * (D / 4); idx += 256) {
        const int r  = idx >> 4;
        const int dv = idx & 15;
        const float4 v = *reinterpret_cast<const float4*>(
            k + (((b * S + j0 + r) * H + h) * D) + 4 * dv);
        HU h0, h1;
        h0.h = __floats2half2_rn(-v.x, -v.y);   // pre-negate: HADD2 acts as SUB
        h1.h = __floats2half2_rn(-v.z, -v.w);
        *reinterpret_cast<uint2*>(ks + r * HSTR + 4 * dv) = make_uint2(h0.u, h1.u);
    }
    __syncthreads();

    const int tx = tid & 15;            // i: i = tx + 16*c, c<2
    const int ty = tid >> 4;            // j: j = ty + 16*e, e<8

    const __half* qb = qs + tx * HSTR;
    const __half* kb = ks + ty * HSTR;

    float2 acc[2][8];
    #pragma unroll
    for (int c = 0; c < 2; ++c)
        #pragma unroll
        for (int e = 0; e < 8; ++e) acc[c][e] = make_float2(0.f, 0.f);

    union U { uint4 u4; __half2 h2[4]; };

    // 4 groups of 16 halves (32B) cover D=64.
    #pragma unroll
    for (int g = 0; g < 4; ++g) {
        U qv[2][2];
        #pragma unroll
        for (int c = 0; c < 2; ++c) {
            qv[c][0].u4 = *reinterpret_cast<const uint4*>(qb + 16 * c * HSTR + g * 16);
            qv[c][1].u4 = *reinterpret_cast<const uint4*>(qb + 16 * c * HSTR + g * 16 + 8);
        }
        // 8 k rows in 4 sub-blocks of 2 to cap register liveness.
        #pragma unroll
        for (int kbk = 0; kbk < 4; ++kbk) {
            U kv[2][2];
            #pragma unroll
            for (int ee = 0; ee < 2; ++ee) {
                const __half* kr = kb + 16 * (2 * kbk + ee) * HSTR + g * 16;
                kv[ee][0].u4 = *reinterpret_cast<const uint4*>(kr);
                kv[ee][1].u4 = *reinterpret_cast<const uint4*>(kr + 8);
            }
            #pragma unroll
            for (int c = 0; c < 2; ++c)
                #pragma unroll
                for (int ee = 0; ee < 2; ++ee) {
                    __half2 s[8];
                    #pragma unroll
                    for (int t = 0; t < 4; ++t)
                        s[t] = __hadd2(qv[c][0].h2[t], kv[ee][0].h2[t]);
                    #pragma unroll
                    for (int t = 0; t < 4; ++t)
                        s[4 + t] = __hadd2(qv[c][1].h2[t], kv[ee][1].h2[t]);
                    // Tree reduce with abs folded into HADD2 source modifiers.
                    const __half2 t0 = __hadd2(__habs2(s[0]), __habs2(s[1]));
                    const __half2 t1 = __hadd2(__habs2(s[2]), __habs2(s[3]));
                    const __half2 t2 = __hadd2(__habs2(s[4]), __habs2(s[5]));
                    const __half2 t3 = __hadd2(__habs2(s[6]), __habs2(s[7]));
                    const __half2 u0 = __hadd2(t0, t1);
                    const __half2 u1 = __hadd2(t2, t3);
                    const __half2 a  = __hadd2(u0, u1);
                    const float2 f = __half22float2(a);     // flush each 16-term group
                    acc[c][2 * kbk + ee].x += f.x;
                    acc[c][2 * kbk + ee].y += f.y;
                }
        }
    }

    // ---- Writeback: out[bh][j][i] = -0.125 * (x + y) ----
    #pragma unroll
    for (int e = 0; e < 8; ++e) {
        const int j = j0 + ty + 16 * e;
        float* orow = out + ((size_t)bh * S + j) * S + i0;
        #pragma unroll
        for (int c = 0; c < 2; ++c)
            orow[tx + 16 * c] = -0.125f * (acc[c][e].x + acc[c][e].y);
    }
}

extern "C" void kernel_launch(void* const* d_in, const int* in_sizes, int n_in,
                              void* d_out, int out_size) {
    const float* q = (const float*)d_in[0];
    const float* k = (const float*)d_in[1];
    float* out     = (float*)d_out;
    dim3 grid(S / TI, S / TJ, 2 * H);   // (16, 4, 16) = 1024 CTAs
    l1attn_kernel<<<grid, 256>>>(q, k, out);
}

// round 12
// speedup vs baseline: 1.4135x; 1.0091x over previous
#include <cuda_runtime.h>
#include <cuda_fp16.h>
#include <cstdint>

constexpr int S = 512, H = 8, D = 64;
constexpr int TI = 32;     // i-tile (output columns)
constexpr int TJ = 128;    // j-tile (output rows)
constexpr int HSTR = 72;   // halves per smem row = 144B: 16B-aligned (LDS.128 legal),
                           // conflict-free phases for tx-strided rows.

__global__ __launch_bounds__(256, 3)
void l1attn_kernel(const float* __restrict__ q, const float* __restrict__ k,
                   float* __restrict__ out) {
    __shared__ __align__(16) __half qs[TI * HSTR];
    __shared__ __align__(16) __half ks[TJ * HSTR];

    const int bh = blockIdx.z;          // b*H + h
    const int b  = bh >> 3;
    const int h  = bh & 7;
    const int i0 = blockIdx.x * TI;
    const int j0 = blockIdx.y * TJ;
    const int tid = threadIdx.x;

    union HU { __half2 h; unsigned u; };

    // ---- Fill smem (float4 LDG.128 -> packed 8B STS): q tile, NEGATED k tile ----
    #pragma unroll
    for (int idx = tid; idx < TI * (D / 4); idx += 256) {
        const int r  = idx >> 4;
        const int dv = idx & 15;
        const float4 v = *reinterpret_cast<const float4*>(
            q + (((b * S + i0 + r) * H + h) * D) + 4 * dv);
        HU h0, h1;
        h0.h = __floats2half2_rn(v.x, v.y);
        h1.h = __floats2half2_rn(v.z, v.w);
        *reinterpret_cast<uint2*>(qs + r * HSTR + 4 * dv) = make_uint2(h0.u, h1.u);
    }
    #pragma unroll
    for (int idx = tid; idx < TJ * (D / 4); idx += 256) {
        const int r  = idx >> 4;
        const int dv = idx & 15;
        const float4 v = *reinterpret_cast<const float4*>(
            k + (((b * S + j0 + r) * H + h) * D) + 4 * dv);
        HU h0, h1;
        h0.h = __floats2half2_rn(-v.x, -v.y);   // pre-negate: HADD2 acts as SUB
        h1.h = __floats2half2_rn(-v.z, -v.w);
        *reinterpret_cast<uint2*>(ks + r * HSTR + 4 * dv) = make_uint2(h0.u, h1.u);
    }
    __syncthreads();

    const int tx = tid & 15;            // i: i = tx + 16*c, c<2
    const int ty = tid >> 4;            // j: j = ty + 16*e, e<8

    const __half* qb = qs + tx * HSTR;
    const __half* kb = ks + ty * HSTR;

    // Scalar fp32 accumulators (16 regs) — halves of each group folded at flush.
    float acc[2][8];
    #pragma unroll
    for (int c = 0; c < 2; ++c)
        #pragma unroll
        for (int e = 0; e < 8; ++e) acc[c][e] = 0.f;

    union U { uint4 u4; __half2 h2[4]; };

    // 4 groups of 16 halves (32B) cover D=64.
    #pragma unroll
    for (int g = 0; g < 4; ++g) {
        U qv[2][2];
        #pragma unroll
        for (int c = 0; c < 2; ++c) {
            qv[c][0].u4 = *reinterpret_cast<const uint4*>(qb + 16 * c * HSTR + g * 16);
            qv[c][1].u4 = *reinterpret_cast<const uint4*>(qb + 16 * c * HSTR + g * 16 + 8);
        }

        // Software pipeline over the 8 k rows: prefetch row e+1, compute row e.
        U kcur[2], knxt[2];
        kcur[0].u4 = *reinterpret_cast<const uint4*>(kb + g * 16);
        kcur[1].u4 = *reinterpret_cast<const uint4*>(kb + g * 16 + 8);

        #pragma unroll
        for (int e = 0; e < 8; ++e) {
            if (e < 7) {
                const __half* kr = kb + 16 * (e + 1) * HSTR + g * 16;
                knxt[0].u4 = *reinterpret_cast<const uint4*>(kr);
                knxt[1].u4 = *reinterpret_cast<const uint4*>(kr + 8);
            }
            #pragma unroll
            for (int c = 0; c < 2; ++c) {
                __half2 s[8];
                #pragma unroll
                for (int t = 0; t < 4; ++t)
                    s[t] = __hadd2(qv[c][0].h2[t], kcur[0].h2[t]);
                #pragma unroll
                for (int t = 0; t < 4; ++t)
                    s[4 + t] = __hadd2(qv[c][1].h2[t], kcur[1].h2[t]);
                // Tree reduce; abs folds into HADD2 source modifiers.
                const __half2 t0 = __hadd2(__habs2(s[0]), __habs2(s[1]));
                const __half2 t1 = __hadd2(__habs2(s[2]), __habs2(s[3]));
                const __half2 t2 = __hadd2(__habs2(s[4]), __habs2(s[5]));
                const __half2 t3 = __hadd2(__habs2(s[6]), __habs2(s[7]));
                const __half2 u0 = __hadd2(t0, t1);
                const __half2 u1 = __hadd2(t2, t3);
                const __half2 a  = __hadd2(u0, u1);
                const float2 f = __half22float2(a);   // flush each 16-term group
                acc[c][e] += f.x + f.y;
            }
            kcur[0].u4 = knxt[0].u4;
            kcur[1].u4 = knxt[1].u4;
        }
    }

    // ---- Writeback: out[bh][j][i] = -0.125 * acc ----
    #pragma unroll
    for (int e = 0; e < 8; ++e) {
        const int j = j0 + ty + 16 * e;
        float* orow = out + ((size_t)bh * S + j) * S + i0;
        #pragma unroll
        for (int c = 0; c < 2; ++c)
            orow[tx + 16 * c] = -0.125f * acc[c][e];
    }
}

extern "C" void kernel_launch(void* const* d_in, const int* in_sizes, int n_in,
                              void* d_out, int out_size) {
    const float* q = (const float*)d_in[0];
    const float* k = (const float*)d_in[1];
    float* out     = (float*)d_out;
    dim3 grid(S / TI, S / TJ, 2 * H);   // (16, 4, 16) = 1024 CTAs
    l1attn_kernel<<<grid, 256>>>(q, k, out);
}